// round 1
// baseline (speedup 1.0000x reference)
#include <cuda_runtime.h>

#define BATCH   4096
#define T_STEPS 64
#define NDIM    128
#define HID     1024
#define PCOLS   256      // used columns of W3 (256..511)
#define DT_C    0.1f

// Scratch state (no allocations allowed)
__device__ float g_s [BATCH * NDIM];   //  2 MB  current state
__device__ float g_h1[BATCH * HID];    // 16 MB  hidden 1
__device__ float g_h2[BATCH * HID];    // 16 MB  hidden 2

// ---------------------------------------------------------------------------
// init: s <- states[:,0,:], out[:,0,:] <- s
// ---------------------------------------------------------------------------
__global__ void init_kernel(const float* __restrict__ states,
                            float* __restrict__ out) {
    int i = blockIdx.x * blockDim.x + threadIdx.x;
    if (i < BATCH * NDIM) {
        int b = i >> 7;          // /128
        int n = i & 127;
        float v = states[(size_t)b * T_STEPS * NDIM + n];   // states[b,0,n]
        g_s[i] = v;
        out[((size_t)b * (T_STEPS + 1)) * NDIM + n] = v;    // out[b,0,n]
    }
}

// ---------------------------------------------------------------------------
// 128x128 tile SGEMM, BK=8, 256 threads, 8x8 microtile, double-buffered smem.
// MODE 1: C = relu(A@B[0:128,:] + bias + a0*B[128,:] + a1*B[129,:])  (K=128)
//         (first layer: z = [s | a] folded as rank-2 bias)
// MODE 2: C = relu(A@B + bias)                                        (K=1024)
// A row-major lda=K, B row-major ldb, C row-major ld=HID.
// ---------------------------------------------------------------------------
template<int MODE>
__global__ __launch_bounds__(256, 2)
void gemm_relu(const float* __restrict__ A, const float* __restrict__ B,
               const float* __restrict__ bias, float* __restrict__ C,
               int K, int ldb, const float* __restrict__ actions, int t)
{
    __shared__ float As[2][8][128];
    __shared__ float Bs[2][8][128];
    const int tid = threadIdx.x;
    const int bm = blockIdx.x, bn = blockIdx.y;
    const int tx = tid & 15, ty = tid >> 4;

    const float* Ab = A + (size_t)bm * 128 * K;
    const float* Bb = B + bn * 128;

    const int aRow = tid >> 1;          // 0..127
    const int aCol = (tid & 1) * 4;     // 0 or 4
    const int bRow = tid >> 5;          // 0..7
    const int bCol = (tid & 31) * 4;    // 0..124

    float4 ar = *(const float4*)(Ab + (size_t)aRow * K + aCol);
    float4 br = *(const float4*)(Bb + (size_t)bRow * ldb + bCol);
    As[0][aCol+0][aRow] = ar.x; As[0][aCol+1][aRow] = ar.y;
    As[0][aCol+2][aRow] = ar.z; As[0][aCol+3][aRow] = ar.w;
    *(float4*)&Bs[0][bRow][bCol] = br;
    __syncthreads();

    float acc[8][8];
    #pragma unroll
    for (int i = 0; i < 8; i++)
        #pragma unroll
        for (int j = 0; j < 8; j++) acc[i][j] = 0.f;

    const int KT = K >> 3;
    int buf = 0;
    for (int kt = 0; kt < KT; kt++) {
        if (kt + 1 < KT) {
            ar = *(const float4*)(Ab + (size_t)aRow * K + (kt + 1) * 8 + aCol);
            br = *(const float4*)(Bb + (size_t)((kt + 1) * 8 + bRow) * ldb + bCol);
        }
        #pragma unroll
        for (int k = 0; k < 8; k++) {
            float af[8], bf[8];
            *(float4*)&af[0] = *(const float4*)&As[buf][k][ty * 8];
            *(float4*)&af[4] = *(const float4*)&As[buf][k][ty * 8 + 4];
            *(float4*)&bf[0] = *(const float4*)&Bs[buf][k][tx * 8];
            *(float4*)&bf[4] = *(const float4*)&Bs[buf][k][tx * 8 + 4];
            #pragma unroll
            for (int i = 0; i < 8; i++)
                #pragma unroll
                for (int j = 0; j < 8; j++)
                    acc[i][j] = fmaf(af[i], bf[j], acc[i][j]);
        }
        if (kt + 1 < KT) {
            buf ^= 1;
            As[buf][aCol+0][aRow] = ar.x; As[buf][aCol+1][aRow] = ar.y;
            As[buf][aCol+2][aRow] = ar.z; As[buf][aCol+3][aRow] = ar.w;
            *(float4*)&Bs[buf][bRow][bCol] = br;
            __syncthreads();
        }
    }

    const int row0 = bm * 128 + ty * 8;
    const int col0 = bn * 128 + tx * 8;

    float bb[8];
    #pragma unroll
    for (int j = 0; j < 8; j++) bb[j] = bias[col0 + j];

    if (MODE == 1) {
        float w0[8], w1[8];
        #pragma unroll
        for (int j = 0; j < 8; j++) {
            w0[j] = B[(size_t)128 * ldb + col0 + j];
            w1[j] = B[(size_t)129 * ldb + col0 + j];
        }
        #pragma unroll
        for (int i = 0; i < 8; i++) {
            int b = row0 + i;
            float a0 = actions[((size_t)b * T_STEPS + t) * 2 + 0];
            float a1 = actions[((size_t)b * T_STEPS + t) * 2 + 1];
            float o[8];
            #pragma unroll
            for (int j = 0; j < 8; j++) {
                float v = acc[i][j] + bb[j] + a0 * w0[j] + a1 * w1[j];
                o[j] = v > 0.f ? v : 0.f;
            }
            *(float4*)&C[(size_t)b * HID + col0]     = *(float4*)&o[0];
            *(float4*)&C[(size_t)b * HID + col0 + 4] = *(float4*)&o[4];
        }
    } else {
        #pragma unroll
        for (int i = 0; i < 8; i++) {
            int b = row0 + i;
            float o[8];
            #pragma unroll
            for (int j = 0; j < 8; j++) {
                float v = acc[i][j] + bb[j];
                o[j] = v > 0.f ? v : 0.f;
            }
            *(float4*)&C[(size_t)b * HID + col0]     = *(float4*)&o[0];
            *(float4*)&C[(size_t)b * HID + col0 + 4] = *(float4*)&o[4];
        }
    }
}

// ---------------------------------------------------------------------------
// GEMM3 fused with state update + output write.
// P[b, c] = (h2 @ W3[:, 256+c]) + b3[256+c],  c in [0,256)
// s_new[b,n] = s[b,n] + DT*(P[b,2n]*a0 + P[b,2n+1]*a1)
// 64x64 tile, BK=8, 256 threads, 4x4 microtile.
// ---------------------------------------------------------------------------
__global__ __launch_bounds__(256)
void gemm_update(const float* __restrict__ A /* g_h2 */,
                 const float* __restrict__ W3,
                 const float* __restrict__ b3,
                 const float* __restrict__ actions,
                 int t, float* __restrict__ out)
{
    __shared__ float As[2][8][64];
    __shared__ float Bs[2][8][64];
    const int tid = threadIdx.x;
    const int bm = blockIdx.x, bn = blockIdx.y;
    const int tx = tid & 15, ty = tid >> 4;

    const float* Ab = A + (size_t)bm * 64 * HID;
    const float* Bb = W3 + 256 + bn * 64;      // ldb = 512, skip dead A-params

    const int aRow = tid >> 2;          // 0..63
    const int aCol = (tid & 3) * 2;     // 0,2,4,6
    const int bRow = tid >> 5;          // 0..7
    const int bCol = (tid & 31) * 2;    // 0..62

    float2 ar = *(const float2*)(Ab + (size_t)aRow * HID + aCol);
    float2 br = *(const float2*)(Bb + (size_t)bRow * 512 + bCol);
    As[0][aCol+0][aRow] = ar.x; As[0][aCol+1][aRow] = ar.y;
    *(float2*)&Bs[0][bRow][bCol] = br;
    __syncthreads();

    float acc[4][4];
    #pragma unroll
    for (int i = 0; i < 4; i++)
        #pragma unroll
        for (int j = 0; j < 4; j++) acc[i][j] = 0.f;

    const int KT = HID >> 3;   // 128
    int buf = 0;
    for (int kt = 0; kt < KT; kt++) {
        if (kt + 1 < KT) {
            ar = *(const float2*)(Ab + (size_t)aRow * HID + (kt + 1) * 8 + aCol);
            br = *(const float2*)(Bb + (size_t)((kt + 1) * 8 + bRow) * 512 + bCol);
        }
        #pragma unroll
        for (int k = 0; k < 8; k++) {
            float af[4], bf[4];
            *(float4*)&af[0] = *(const float4*)&As[buf][k][ty * 4];
            *(float4*)&bf[0] = *(const float4*)&Bs[buf][k][tx * 4];
            #pragma unroll
            for (int i = 0; i < 4; i++)
                #pragma unroll
                for (int j = 0; j < 4; j++)
                    acc[i][j] = fmaf(af[i], bf[j], acc[i][j]);
        }
        if (kt + 1 < KT) {
            buf ^= 1;
            As[buf][aCol+0][aRow] = ar.x; As[buf][aCol+1][aRow] = ar.y;
            *(float2*)&Bs[buf][bRow][bCol] = br;
            __syncthreads();
        }
    }

    const int row0 = bm * 64 + ty * 4;
    const int c0   = bn * 64 + tx * 4;     // P-column base, multiple of 4
    float bb[4];
    #pragma unroll
    for (int j = 0; j < 4; j++) bb[j] = b3[256 + c0 + j];

    const int n0 = c0 >> 1;                // output state index base (2 per thread)
    #pragma unroll
    for (int i = 0; i < 4; i++) {
        int b = row0 + i;
        float a0 = actions[((size_t)b * T_STEPS + t) * 2 + 0];
        float a1 = actions[((size_t)b * T_STEPS + t) * 2 + 1];
        float p0 = acc[i][0] + bb[0];
        float p1 = acc[i][1] + bb[1];
        float p2 = acc[i][2] + bb[2];
        float p3 = acc[i][3] + bb[3];
        float s0v = g_s[(size_t)b * NDIM + n0];
        float s1v = g_s[(size_t)b * NDIM + n0 + 1];
        float ns0 = fmaf(DT_C, fmaf(p0, a0, p1 * a1), s0v);
        float ns1 = fmaf(DT_C, fmaf(p2, a0, p3 * a1), s1v);
        g_s[(size_t)b * NDIM + n0]     = ns0;
        g_s[(size_t)b * NDIM + n0 + 1] = ns1;
        size_t ob = ((size_t)b * (T_STEPS + 1) + t + 1) * NDIM;
        out[ob + n0]     = ns0;
        out[ob + n0 + 1] = ns1;
    }
}

// ---------------------------------------------------------------------------
extern "C" void kernel_launch(void* const* d_in, const int* in_sizes, int n_in,
                              void* d_out, int out_size) {
    const float* states  = (const float*)d_in[0];
    const float* actions = (const float*)d_in[1];
    const float* W1 = (const float*)d_in[2];
    const float* b1 = (const float*)d_in[3];
    const float* W2 = (const float*)d_in[4];
    const float* b2 = (const float*)d_in[5];
    const float* W3 = (const float*)d_in[6];
    const float* b3 = (const float*)d_in[7];
    float* out = (float*)d_out;

    float *ps, *ph1, *ph2;
    cudaGetSymbolAddress((void**)&ps,  g_s);
    cudaGetSymbolAddress((void**)&ph1, g_h1);
    cudaGetSymbolAddress((void**)&ph2, g_h2);

    dim3 blk(256);
    dim3 g12(32, 8);   // 4096/128 x 1024/128
    dim3 g3(64, 4);    // 4096/64  x 256/64

    init_kernel<<<(BATCH * NDIM + 255) / 256, 256>>>(states, out);
    for (int t = 0; t < T_STEPS; t++) {
        gemm_relu<1><<<g12, blk>>>(ps,  W1, b1, ph1, 128,  HID, actions, t);
        gemm_relu<2><<<g12, blk>>>(ph1, W2, b2, ph2, 1024, HID, nullptr, 0);
        gemm_update<<<g3, blk>>>(ph2, W3, b3, actions, t, out);
    }
}

// round 3
// speedup vs baseline: 2.8578x; 2.8578x over previous
#include <cuda_runtime.h>
#include <cstdint>

#define BATCH   4096
#define T_STEPS 64
#define NDIM    128
#define HID     1024
#define DT_C    0.1f

// ---------------- device scratch (no allocations allowed) -------------------
__device__ float g_s  [BATCH * NDIM];   // fp32 exact state (plain row-major)
__device__ float g_sr [BATCH * NDIM];   // tf32 state, A-tiled (K=128)
__device__ float g_h1 [BATCH * HID];    // A-tiled (K=1024)
__device__ float g_h2 [BATCH * HID];    // A-tiled (K=1024)
__device__ float g_W1T[HID * NDIM];     // B-tiled N=1024,K=128
__device__ float g_W2T[HID * HID];      // B-tiled N=1024,K=1024
__device__ float g_W3T[256 * HID];      // B-tiled N=256, K=1024 (cols 256..511)

// ---------------- helpers ----------------------------------------------------
__device__ __forceinline__ float to_tf32(float x) {
    float r; asm("cvt.rna.tf32.f32 %0, %1;" : "=f"(r) : "f"(x)); return r;
}
__device__ __forceinline__ uint32_t smem_u32(const void* p) {
    uint32_t a;
    asm("{ .reg .u64 t; cvta.to.shared.u64 t, %1; cvt.u32.u64 %0, t; }" : "=r"(a) : "l"(p));
    return a;
}
__device__ __forceinline__ void cp16(uint32_t dst, const float* src) {
    asm volatile("cp.async.cg.shared.global [%0], [%1], 16;" :: "r"(dst), "l"(src));
}
__device__ __forceinline__ void cp_commit() { asm volatile("cp.async.commit_group;"); }
template<int N> __device__ __forceinline__ void cp_wait() {
    asm volatile("cp.async.wait_group %0;" :: "n"(N) : "memory");
}

// mma.sync m16n8k8 tf32: d += a*b
__device__ __forceinline__ void mma8(float (&d)[4], const uint32_t (&a)[4],
                                     const uint32_t (&b)[2]) {
    asm volatile(
        "mma.sync.aligned.m16n8k8.row.col.f32.tf32.tf32.f32 "
        "{%0,%1,%2,%3}, {%4,%5,%6,%7}, {%8,%9}, {%0,%1,%2,%3};"
        : "+f"(d[0]), "+f"(d[1]), "+f"(d[2]), "+f"(d[3])
        : "r"(a[0]), "r"(a[1]), "r"(a[2]), "r"(a[3]), "r"(b[0]), "r"(b[1]));
}

// Fragment-native tiled layouts.
// A (M x K): 16x8 blocks; within block: lane=(m&7)*4+(k&3), j=((m>>3)&1)|(((k>>2)&1)<<1)
__device__ __forceinline__ size_t a_idx(int m, int k, int K) {
    return ((size_t)(m >> 4) * (K >> 3) + (k >> 3)) * 128
         + (((m & 7) * 4 + (k & 3)) << 2) + ((m >> 3) & 1) + (((k >> 2) & 1) << 1);
}
// B (N x K): 8x8 blocks; lane=(n&7)*4+(k&3), j=(k>>2)&1
__device__ __forceinline__ size_t b_idx(int n, int k, int K) {
    return ((size_t)(n >> 3) * (K >> 3) + (k >> 3)) * 64
         + (((n & 7) * 4 + (k & 3)) << 1) + ((k >> 2) & 1);
}

// ---------------------------------------------------------------------------
__global__ void init_kernel(const float* __restrict__ states, float* __restrict__ out) {
    int i = blockIdx.x * blockDim.x + threadIdx.x;
    if (i < BATCH * NDIM) {
        int b = i >> 7, n = i & 127;
        float v = states[(size_t)b * T_STEPS * NDIM + n];
        g_s[i] = v;
        g_sr[a_idx(b, n, NDIM)] = to_tf32(v);
        out[((size_t)b * (T_STEPS + 1)) * NDIM + n] = v;
    }
}

// weights: raw [K][Nfull] (col offset n0) -> B-tiled [N x K], tf32-rounded
__global__ void prep_w(const float* __restrict__ in, float* __restrict__ outp,
                       int K, int Nfull, int n0, int N) {
    int idx = blockIdx.x * blockDim.x + threadIdx.x;
    if (idx < K * N) {
        int n = idx % N, k = idx / N;
        outp[b_idx(n, k, K)] = to_tf32(in[(size_t)k * Nfull + n0 + n]);
    }
}

// ---------------------------------------------------------------------------
// tf32 mma.sync GEMM: block 128x128, 8 warps (2m x 4n), warp tile 64x32,
// K-chunk 32, 4-stage cp.async pipeline. A,B in fragment-native tiled layout.
// MODE 0: C = tf32(relu(D+bias))                      -> A-tiled (layer 2)
// MODE 1: + a0*W1[128,:] + a1*W1[129,:] rank-2 term   -> A-tiled (layer 1)
// MODE 2: state update: P=D+bias; s+=DT*(P_ev*a0+P_od*a1); write s, sr, out
// ---------------------------------------------------------------------------
template<int MODE>
__global__ void __launch_bounds__(256, 1)
mma_gemm(const float* __restrict__ A, const float* __restrict__ Bt,
         const float* __restrict__ bias, float* __restrict__ C, int K,
         const float* __restrict__ W1raw, const float* __restrict__ actions,
         int t, float* __restrict__ out)
{
    constexpr int OFF   = 4096;       // header bytes
    constexpr int STAGE = 32768;      // 16KB A + 16KB B

    extern __shared__ char smem[];
    float* hS = (float*)smem;         // [0:128) bias, [128) a0, [256) a1, [384) w0, [512) w1
    const uint32_t sb = smem_u32(smem);
    const int tid = threadIdx.x, lane = tid & 31, warp = tid >> 5;
    const int wm = warp & 1, wn = warp >> 1;
    const int bm = blockIdx.x, bn = blockIdx.y;
    const int KT = K >> 5;
    const int KB = K >> 3;

    if (tid < 128) {
        hS[tid] = bias[bn * 128 + tid];
        if (MODE != 0) {
            int m = bm * 128 + tid;
            const float* ap = actions + ((size_t)m * T_STEPS + t) * 2;
            hS[128 + tid] = ap[0];
            hS[256 + tid] = ap[1];
        }
        if (MODE == 1) {
            hS[384 + tid] = W1raw[(size_t)128 * HID + bn * 128 + tid];
            hS[512 + tid] = W1raw[(size_t)129 * HID + bn * 128 + tid];
        }
    }

    const float* Ab = A;
    const float* Bb = Bt;

    auto load_stage = [&](int ks) {
        uint32_t sa = sb + OFF + (uint32_t)(ks & 3) * STAGE;
        #pragma unroll
        for (int v = tid; v < 1024; v += 256) {               // A: 8 mb x 512 floats
            int i = v >> 7, inner = v & 127;
            cp16(sa + (uint32_t)v * 16,
                 Ab + ((size_t)(bm * 8 + i) * KB + ks * 4) * 128 + inner * 4);
        }
        uint32_t sB = sa + 16384;
        #pragma unroll
        for (int v = tid; v < 1024; v += 256) {               // B: 16 nb x 256 floats
            int j = v >> 6, inner = v & 63;
            cp16(sB + (uint32_t)v * 16,
                 Bb + ((size_t)(bn * 16 + j) * KB + ks * 4) * 64 + inner * 4);
        }
        cp_commit();
    };

    float acc[4][4][4];
    #pragma unroll
    for (int i = 0; i < 4; i++)
        #pragma unroll
        for (int j = 0; j < 4; j++)
            #pragma unroll
            for (int q = 0; q < 4; q++) acc[i][j][q] = 0.f;

    load_stage(0); load_stage(1); load_stage(2);

    for (int kt = 0; kt < KT; kt++) {
        int ahead = KT - 1 - kt;
        if (ahead >= 2) cp_wait<2>();
        else if (ahead == 1) cp_wait<1>();
        else cp_wait<0>();
        __syncthreads();

        if (kt + 3 < KT) load_stage(kt + 3);

        uint32_t sa = sb + OFF + (uint32_t)(kt & 3) * STAGE;
        uint32_t sB = sa + 16384;
        #pragma unroll
        for (int kk = 0; kk < 4; kk++) {
            uint32_t afr[4][4], bfr[4][2];
            #pragma unroll
            for (int mf = 0; mf < 4; mf++) {
                uint32_t ad = sa + (uint32_t)(((wm * 4 + mf) * 4 + kk) * 512) + lane * 16;
                asm volatile("ld.shared.v4.b32 {%0,%1,%2,%3}, [%4];"
                    : "=r"(afr[mf][0]), "=r"(afr[mf][1]), "=r"(afr[mf][2]), "=r"(afr[mf][3])
                    : "r"(ad));
            }
            #pragma unroll
            for (int nf = 0; nf < 4; nf++) {
                uint32_t bd = sB + (uint32_t)(((wn * 4 + nf) * 4 + kk) * 256) + lane * 8;
                asm volatile("ld.shared.v2.b32 {%0,%1}, [%2];"
                    : "=r"(bfr[nf][0]), "=r"(bfr[nf][1]) : "r"(bd));
            }
            #pragma unroll
            for (int mf = 0; mf < 4; mf++)
                #pragma unroll
                for (int nf = 0; nf < 4; nf++)
                    mma8(acc[mf][nf], afr[mf], bfr[nf]);
        }
    }
    __syncthreads();   // done reading stages; epilogue reuses that smem

    const int r = lane >> 2, cq = lane & 3;

    if (MODE == 2) {
        #pragma unroll
        for (int mf = 0; mf < 4; mf++) {
            int ml = wm * 64 + mf * 16 + r;
            int m = bm * 128 + ml;
            float a0L = hS[128 + ml],     a1L = hS[256 + ml];
            float a0H = hS[128 + ml + 8], a1H = hS[256 + ml + 8];
            #pragma unroll
            for (int nf = 0; nf < 4; nf++) {
                int col = wn * 32 + nf * 8 + cq * 2;
                int n = bn * 64 + (col >> 1);
                float p0 = acc[mf][nf][0] + hS[col];
                float p1 = acc[mf][nf][1] + hS[col + 1];
                float p2 = acc[mf][nf][2] + hS[col];
                float p3 = acc[mf][nf][3] + hS[col + 1];
                float sv0 = g_s[(size_t)m * NDIM + n];
                float sv1 = g_s[(size_t)(m + 8) * NDIM + n];
                float ns0 = fmaf(DT_C, fmaf(p0, a0L, p1 * a1L), sv0);
                float ns1 = fmaf(DT_C, fmaf(p2, a0H, p3 * a1H), sv1);
                g_s[(size_t)m * NDIM + n] = ns0;
                g_s[(size_t)(m + 8) * NDIM + n] = ns1;
                g_sr[a_idx(m, n, NDIM)] = to_tf32(ns0);
                g_sr[a_idx(m + 8, n, NDIM)] = to_tf32(ns1);
                out[((size_t)m * (T_STEPS + 1) + t + 1) * NDIM + n] = ns0;
                out[((size_t)(m + 8) * (T_STEPS + 1) + t + 1) * NDIM + n] = ns1;
            }
        }
        return;
    }

    // MODE 0/1: bias(+rank-2 action)+relu+tf32, stage A-tiled in smem, copy out
    float* eS = (float*)(smem + OFF);
    #pragma unroll
    for (int mf = 0; mf < 4; mf++) {
        int ml = wm * 64 + mf * 16 + r;
        float a0L = 0.f, a1L = 0.f, a0H = 0.f, a1H = 0.f;
        if (MODE == 1) {
            a0L = hS[128 + ml];     a1L = hS[256 + ml];
            a0H = hS[128 + ml + 8]; a1H = hS[256 + ml + 8];
        }
        #pragma unroll
        for (int nf = 0; nf < 4; nf++) {
            int nl0 = wn * 32 + nf * 8 + cq * 2;
            int nl1 = nl0 + 1;
            float v00 = acc[mf][nf][0] + hS[nl0];
            float v01 = acc[mf][nf][1] + hS[nl1];
            float v10 = acc[mf][nf][2] + hS[nl0];
            float v11 = acc[mf][nf][3] + hS[nl1];
            if (MODE == 1) {
                v00 += a0L * hS[384 + nl0] + a1L * hS[512 + nl0];
                v01 += a0L * hS[384 + nl1] + a1L * hS[512 + nl1];
                v10 += a0H * hS[384 + nl0] + a1H * hS[512 + nl0];
                v11 += a0H * hS[384 + nl1] + a1H * hS[512 + nl1];
            }
            v00 = to_tf32(v00 > 0.f ? v00 : 0.f);
            v01 = to_tf32(v01 > 0.f ? v01 : 0.f);
            v10 = to_tf32(v10 > 0.f ? v10 : 0.f);
            v11 = to_tf32(v11 > 0.f ? v11 : 0.f);
            // tiled local idx; (v00,v10) and (v01,v11) are j-adjacent pairs
            int base0 = (((ml >> 4) * 16 + (nl0 >> 3)) << 7)
                      + (((ml & 7) * 4 + (nl0 & 3)) << 2) + (((nl0 >> 2) & 1) << 1);
            *(float2*)&eS[base0]     = make_float2(v00, v10);
            *(float2*)&eS[base0 + 4] = make_float2(v01, v11);
        }
    }
    __syncthreads();
    const float4* e4 = (const float4*)eS;
    float4* C4 = (float4*)C;
    #pragma unroll
    for (int v = tid; v < 4096; v += 256) {
        int mbL = v >> 9, inner = v & 511;
        C4[((size_t)(bm * 8 + mbL) * (HID >> 3) + bn * 16) * 32 + inner] = e4[v];
    }
}

// ---------------------------------------------------------------------------
extern "C" void kernel_launch(void* const* d_in, const int* in_sizes, int n_in,
                              void* d_out, int out_size) {
    const float* states  = (const float*)d_in[0];
    const float* actions = (const float*)d_in[1];
    const float* W1 = (const float*)d_in[2];
    const float* b1 = (const float*)d_in[3];
    const float* W2 = (const float*)d_in[4];
    const float* b2 = (const float*)d_in[5];
    const float* W3 = (const float*)d_in[6];
    const float* b3 = (const float*)d_in[7];
    float* out = (float*)d_out;

    float *psr, *ph1, *ph2, *pw1t, *pw2t, *pw3t;
    cudaGetSymbolAddress((void**)&psr,  g_sr);
    cudaGetSymbolAddress((void**)&ph1,  g_h1);
    cudaGetSymbolAddress((void**)&ph2,  g_h2);
    cudaGetSymbolAddress((void**)&pw1t, g_W1T);
    cudaGetSymbolAddress((void**)&pw2t, g_W2T);
    cudaGetSymbolAddress((void**)&pw3t, g_W3T);

    const int SMEM = 4096 + 4 * 32768;   // 135168
    cudaFuncSetAttribute(mma_gemm<0>, cudaFuncAttributeMaxDynamicSharedMemorySize, SMEM);
    cudaFuncSetAttribute(mma_gemm<1>, cudaFuncAttributeMaxDynamicSharedMemorySize, SMEM);
    cudaFuncSetAttribute(mma_gemm<2>, cudaFuncAttributeMaxDynamicSharedMemorySize, SMEM);

    init_kernel<<<(BATCH * NDIM + 255) / 256, 256>>>(states, out);
    prep_w<<<(128  * 1024 + 255) / 256, 256>>>(W1, pw1t, 128,  1024, 0,   1024);
    prep_w<<<(1024 * 1024 + 255) / 256, 256>>>(W2, pw2t, 1024, 1024, 0,   1024);
    prep_w<<<(1024 * 256  + 255) / 256, 256>>>(W3, pw3t, 1024, 512,  256, 256);

    for (int t = 0; t < T_STEPS; t++) {
        mma_gemm<1><<<dim3(32, 8), 256, SMEM>>>(psr, pw1t, b1, ph1, 128,
                                                W1, actions, t, nullptr);
        mma_gemm<0><<<dim3(32, 8), 256, SMEM>>>(ph1, pw2t, b2, ph2, 1024,
                                                nullptr, nullptr, 0, nullptr);
        mma_gemm<2><<<dim3(32, 2), 256, SMEM>>>(ph2, pw3t, b3 + 256, nullptr, 1024,
                                                nullptr, actions, t, out);
    }
}

// round 4
// speedup vs baseline: 5.9190x; 2.0712x over previous
#include <cuda_runtime.h>
#include <cuda_fp16.h>
#include <cstdint>

#define BATCH   4096
#define T_STEPS 64
#define NDIM    128
#define HID     1024
#define DT_C    0.1f

// ---------------- device scratch (no allocations allowed) -------------------
__device__ float g_s [BATCH * NDIM];                    // fp32 exact state
__device__ __align__(16) __half g_sr [BATCH * NDIM];    // fp16 state, A-tiled (K=128)
__device__ __align__(16) __half g_h1 [BATCH * HID];     // A-tiled (K=1024)
__device__ __align__(16) __half g_h2 [BATCH * HID];     // A-tiled (K=1024)
__device__ __align__(16) __half g_W1T[HID * NDIM];      // B-tiled N=1024,K=128
__device__ __align__(16) __half g_W2T[HID * HID];       // B-tiled N=1024,K=1024
__device__ __align__(16) __half g_W3T[256 * HID];       // B-tiled N=256,K=1024 (W3 cols 256..511)

// ---------------- helpers ----------------------------------------------------
__device__ __forceinline__ uint32_t smem_u32(const void* p) {
    uint32_t a;
    asm("{ .reg .u64 t; cvta.to.shared.u64 t, %1; cvt.u32.u64 %0, t; }" : "=r"(a) : "l"(p));
    return a;
}
__device__ __forceinline__ void cp16(uint32_t dst, const void* src) {
    asm volatile("cp.async.cg.shared.global [%0], [%1], 16;" :: "r"(dst), "l"(src));
}
__device__ __forceinline__ void cp_commit() { asm volatile("cp.async.commit_group;"); }
template<int N> __device__ __forceinline__ void cp_wait() {
    asm volatile("cp.async.wait_group %0;" :: "n"(N) : "memory");
}

// mma.sync m16n8k16 fp16 in, fp32 acc: d += a*b
__device__ __forceinline__ void mma16(float (&d)[4], const uint32_t (&a)[4],
                                      const uint32_t (&b)[2]) {
    asm volatile(
        "mma.sync.aligned.m16n8k16.row.col.f32.f16.f16.f32 "
        "{%0,%1,%2,%3}, {%4,%5,%6,%7}, {%8,%9}, {%0,%1,%2,%3};"
        : "+f"(d[0]), "+f"(d[1]), "+f"(d[2]), "+f"(d[3])
        : "r"(a[0]), "r"(a[1]), "r"(a[2]), "r"(a[3]), "r"(b[0]), "r"(b[1]));
}

// Fragment-native tiled layouts (half element index).
// A: 16x16 blocks. lane=(m&7)*4+((k&7)>>1), j=((m>>3)&1)|(((k>>3)&1)<<1), h=k&1
__device__ __forceinline__ size_t a_idx_h(int m, int k, int K) {
    return ((size_t)(m >> 4) * (K >> 4) + (k >> 4)) * 256
         + (((m & 7) * 4 + ((k & 7) >> 1)) << 3)
         + ((((m >> 3) & 1) | (((k >> 3) & 1) << 1)) << 1) + (k & 1);
}
// B: 8x16 blocks. lane=(n&7)*4+((k&7)>>1), j=(k>>3)&1, h=k&1
__device__ __forceinline__ size_t b_idx_h(int n, int k, int K) {
    return ((size_t)(n >> 3) * (K >> 4) + (k >> 4)) * 128
         + (((n & 7) * 4 + ((k & 7) >> 1)) << 2)
         + (((k >> 3) & 1) << 1) + (k & 1);
}

// ---------------------------------------------------------------------------
__global__ void init_kernel(const float* __restrict__ states, float* __restrict__ out) {
    int i = blockIdx.x * blockDim.x + threadIdx.x;
    if (i < BATCH * NDIM) {
        int b = i >> 7, n = i & 127;
        float v = states[(size_t)b * T_STEPS * NDIM + n];
        g_s[i] = v;
        g_sr[a_idx_h(b, n, NDIM)] = __float2half_rn(v);
        out[((size_t)b * (T_STEPS + 1)) * NDIM + n] = v;
    }
}

// weights: raw [K][Nfull] (col offset n0) -> B-tiled [N x K] fp16
__global__ void prep_w(const float* __restrict__ in, __half* __restrict__ outp,
                       int K, int Nfull, int n0, int N) {
    int idx = blockIdx.x * blockDim.x + threadIdx.x;
    if (idx < K * N) {
        int n = idx % N, k = idx / N;
        outp[b_idx_h(n, k, K)] = __float2half_rn(in[(size_t)k * Nfull + n0 + n]);
    }
}

// ---------------------------------------------------------------------------
// fp16 mma.sync GEMM. Block tile 128 x NT, 8 warps, K-chunk 32, 4-stage pipe.
// NT=128: warps 2m x 4n (warp 64x32).  NT=64: warps 4m x 2n (warp 32x32).
// MODE 0: C = fp16(relu(D+bias))                       (layer 2)
// MODE 1: + a0*W1[128,:] + a1*W1[129,:] rank-2 fold    (layer 1)
// MODE 2: P=D+bias; s += DT*(P_even*a0+P_odd*a1); write s, sr, out
// ---------------------------------------------------------------------------
template<int MODE, int NT>
__global__ void __launch_bounds__(256, 2)
mma_gemm(const __half* __restrict__ A, const __half* __restrict__ Bt,
         const float* __restrict__ bias, __half* __restrict__ C, int K,
         const float* __restrict__ W1raw, const float* __restrict__ actions,
         int t, float* __restrict__ out)
{
    constexpr int OFF     = 4096;                        // header bytes
    constexpr int A_BYTES = 8192;                        // 128 x 32 fp16
    constexpr int B_BYTES = NT * 32 * 2;
    constexpr int STAGE   = A_BYTES + B_BYTES;
    constexpr int MF      = (NT == 128) ? 4 : 2;
    constexpr int NBLK    = NT / 8;                      // n-blocks per CTA tile

    extern __shared__ char smem[];
    float* hS = (float*)smem;   // [0:128) bias, [128) a0, [256) a1, [384) w0, [512) w1
    const uint32_t sb = smem_u32(smem);
    const int tid = threadIdx.x, lane = tid & 31, warp = tid >> 5;
    const int wm = (NT == 128) ? (warp & 1) : (warp >> 1);
    const int wn = (NT == 128) ? (warp >> 1) : (warp & 1);
    const int bm = blockIdx.x, bn = blockIdx.y;
    const int KT  = K >> 5;          // 32-k chunks
    const int KB16 = K >> 4;         // 16-k blocks per row

    if (tid < NT)  hS[tid] = bias[bn * NT + tid];
    if (tid < 128 && MODE != 0) {
        int m = bm * 128 + tid;
        const float* ap = actions + ((size_t)m * T_STEPS + t) * 2;
        hS[128 + tid] = ap[0];
        hS[256 + tid] = ap[1];
    }
    if (tid < NT && MODE == 1) {
        hS[384 + tid] = W1raw[(size_t)128 * HID + bn * NT + tid];
        hS[512 + tid] = W1raw[(size_t)129 * HID + bn * NT + tid];
    }

    auto load_stage = [&](int ks) {
        uint32_t sa = sb + OFF + (uint32_t)(ks & 3) * STAGE;
        // A: 8 m-blocks x 1024B (two adjacent 16k-blocks contiguous)
        #pragma unroll
        for (int v = tid; v < 512; v += 256) {
            int i = v >> 6, inner = v & 63;
            cp16(sa + (uint32_t)v * 16,
                 A + ((size_t)(bm * 8 + i) * KB16 + 2 * ks) * 256 + inner * 8);
        }
        uint32_t sB = sa + A_BYTES;
        // B: NBLK n-blocks x 512B
        #pragma unroll
        for (int v = tid; v < NBLK * 32; v += 256) {
            int j = v >> 5, inner = v & 31;
            cp16(sB + (uint32_t)v * 16,
                 Bt + ((size_t)(bn * NBLK + j) * KB16 + 2 * ks) * 128 + inner * 8);
        }
        cp_commit();
    };

    float acc[MF][4][4];
    #pragma unroll
    for (int i = 0; i < MF; i++)
        #pragma unroll
        for (int j = 0; j < 4; j++)
            #pragma unroll
            for (int q = 0; q < 4; q++) acc[i][j][q] = 0.f;

    load_stage(0); load_stage(1); load_stage(2);

    for (int kt = 0; kt < KT; kt++) {
        int ahead = KT - 1 - kt;
        if (ahead >= 2) cp_wait<2>();
        else if (ahead == 1) cp_wait<1>();
        else cp_wait<0>();
        __syncthreads();

        if (kt + 3 < KT) load_stage(kt + 3);

        uint32_t sa = sb + OFF + (uint32_t)(kt & 3) * STAGE;
        uint32_t sB = sa + A_BYTES;
        #pragma unroll
        for (int kk = 0; kk < 2; kk++) {
            uint32_t afr[MF][4], bfr[4][2];
            #pragma unroll
            for (int mf = 0; mf < MF; mf++) {
                uint32_t ad = sa + (uint32_t)((wm * MF + mf) * 1024 + kk * 512) + lane * 16;
                asm volatile("ld.shared.v4.b32 {%0,%1,%2,%3}, [%4];"
                    : "=r"(afr[mf][0]), "=r"(afr[mf][1]), "=r"(afr[mf][2]), "=r"(afr[mf][3])
                    : "r"(ad));
            }
            #pragma unroll
            for (int nf = 0; nf < 4; nf++) {
                uint32_t bd = sB + (uint32_t)((wn * 4 + nf) * 512 + kk * 256) + lane * 8;
                asm volatile("ld.shared.v2.b32 {%0,%1}, [%2];"
                    : "=r"(bfr[nf][0]), "=r"(bfr[nf][1]) : "r"(bd));
            }
            #pragma unroll
            for (int mf = 0; mf < MF; mf++)
                #pragma unroll
                for (int nf = 0; nf < 4; nf++)
                    mma16(acc[mf][nf], afr[mf], bfr[nf]);
        }
    }
    __syncthreads();   // stage smem free; epilogue reuses it

    const int r = lane >> 2, tig = lane & 3;

    if (MODE == 2) {
        #pragma unroll
        for (int mf = 0; mf < MF; mf++) {
            int ml = wm * (MF * 16) + mf * 16 + r;
            int m = bm * 128 + ml;
            float a0L = hS[128 + ml],     a1L = hS[256 + ml];
            float a0H = hS[128 + ml + 8], a1H = hS[256 + ml + 8];
            #pragma unroll
            for (int nf = 0; nf < 4; nf++) {
                int nl0 = wn * 32 + nf * 8 + tig * 2;
                int n = bn * (NT >> 1) + (nl0 >> 1);
                float p0 = acc[mf][nf][0] + hS[nl0];
                float p1 = acc[mf][nf][1] + hS[nl0 + 1];
                float p2 = acc[mf][nf][2] + hS[nl0];
                float p3 = acc[mf][nf][3] + hS[nl0 + 1];
                float sv0 = g_s[(size_t)m * NDIM + n];
                float sv1 = g_s[(size_t)(m + 8) * NDIM + n];
                float ns0 = fmaf(DT_C, fmaf(p0, a0L, p1 * a1L), sv0);
                float ns1 = fmaf(DT_C, fmaf(p2, a0H, p3 * a1H), sv1);
                g_s[(size_t)m * NDIM + n] = ns0;
                g_s[(size_t)(m + 8) * NDIM + n] = ns1;
                g_sr[a_idx_h(m, n, NDIM)] = __float2half_rn(ns0);
                g_sr[a_idx_h(m + 8, n, NDIM)] = __float2half_rn(ns1);
                out[((size_t)m * (T_STEPS + 1) + t + 1) * NDIM + n] = ns0;
                out[((size_t)(m + 8) * (T_STEPS + 1) + t + 1) * NDIM + n] = ns1;
            }
        }
        return;
    }

    // MODE 0/1: bias(+rank-2)+relu -> fp16, stage A-tiled in smem, copy out
    __half* eS = (__half*)(smem + OFF);
    #pragma unroll
    for (int mf = 0; mf < MF; mf++) {
        int ml = wm * (MF * 16) + mf * 16 + r;
        float a0L = 0.f, a1L = 0.f, a0H = 0.f, a1H = 0.f;
        if (MODE == 1) {
            a0L = hS[128 + ml];     a1L = hS[256 + ml];
            a0H = hS[128 + ml + 8]; a1H = hS[256 + ml + 8];
        }
        #pragma unroll
        for (int nf = 0; nf < 4; nf++) {
            int nl0 = wn * 32 + nf * 8 + tig * 2;
            float v00 = acc[mf][nf][0] + hS[nl0];
            float v01 = acc[mf][nf][1] + hS[nl0 + 1];
            float v10 = acc[mf][nf][2] + hS[nl0];
            float v11 = acc[mf][nf][3] + hS[nl0 + 1];
            if (MODE == 1) {
                v00 += a0L * hS[384 + nl0]     + a1L * hS[512 + nl0];
                v01 += a0L * hS[384 + nl0 + 1] + a1L * hS[512 + nl0 + 1];
                v10 += a0H * hS[384 + nl0]     + a1H * hS[512 + nl0];
                v11 += a0H * hS[384 + nl0 + 1] + a1H * hS[512 + nl0 + 1];
            }
            v00 = v00 > 0.f ? v00 : 0.f;  v01 = v01 > 0.f ? v01 : 0.f;
            v10 = v10 > 0.f ? v10 : 0.f;  v11 = v11 > 0.f ? v11 : 0.f;
            // one 8B store covers (row ml, j=0) and (row ml+8, j=1)
            __half2 lo = __floats2half2_rn(v00, v01);
            __half2 hi = __floats2half2_rn(v10, v11);
            int blk = (ml >> 4) * (NT >> 4) + (nl0 >> 4);
            size_t off = (size_t)blk * 256 + lane * 8 + ((nl0 >> 3) & 1) * 4;
            *(uint2*)&eS[off] = make_uint2(*(uint32_t*)&lo, *(uint32_t*)&hi);
        }
    }
    __syncthreads();
    // copy staging -> global A-tiled (per m-block: NT/16 blocks x 512B contiguous)
    const int KOUT = HID >> 4;               // output layout K-blocks per row
    const int CH16 = (128 * NT * 2) / 16;    // 16B chunks
    const uint4* e4 = (const uint4*)eS;
    #pragma unroll
    for (int v = tid; v < CH16; v += 256) {
        int perMB = (NT * 2) / 16 * 16;      // 16B chunks per m-block = NT*2
        int mbL = v / (NT * 2), inner = v % (NT * 2);
        (void)perMB;
        *(uint4*)&C[((size_t)(bm * 8 + mbL) * KOUT + bn * (NT >> 4)) * 256 + inner * 8]
            = e4[v];
    }
}

// ---------------------------------------------------------------------------
extern "C" void kernel_launch(void* const* d_in, const int* in_sizes, int n_in,
                              void* d_out, int out_size) {
    const float* states  = (const float*)d_in[0];
    const float* actions = (const float*)d_in[1];
    const float* W1 = (const float*)d_in[2];
    const float* b1 = (const float*)d_in[3];
    const float* W2 = (const float*)d_in[4];
    const float* b2 = (const float*)d_in[5];
    const float* W3 = (const float*)d_in[6];
    const float* b3 = (const float*)d_in[7];
    float* out = (float*)d_out;

    __half *psr, *ph1, *ph2, *pw1t, *pw2t, *pw3t;
    cudaGetSymbolAddress((void**)&psr,  g_sr);
    cudaGetSymbolAddress((void**)&ph1,  g_h1);
    cudaGetSymbolAddress((void**)&ph2,  g_h2);
    cudaGetSymbolAddress((void**)&pw1t, g_W1T);
    cudaGetSymbolAddress((void**)&pw2t, g_W2T);
    cudaGetSymbolAddress((void**)&pw3t, g_W3T);

    const int SMEM128 = 4096 + 4 * (8192 + 8192);   // 69632
    const int SMEM64  = 4096 + 4 * (8192 + 4096);   // 53248
    cudaFuncSetAttribute(mma_gemm<0,128>, cudaFuncAttributeMaxDynamicSharedMemorySize, SMEM128);
    cudaFuncSetAttribute(mma_gemm<1,128>, cudaFuncAttributeMaxDynamicSharedMemorySize, SMEM128);
    cudaFuncSetAttribute(mma_gemm<2,64>,  cudaFuncAttributeMaxDynamicSharedMemorySize, SMEM64);

    init_kernel<<<(BATCH * NDIM + 255) / 256, 256>>>(states, out);
    prep_w<<<(128  * 1024 + 255) / 256, 256>>>(W1, pw1t, 128,  1024, 0,   1024);
    prep_w<<<(1024 * 1024 + 255) / 256, 256>>>(W2, pw2t, 1024, 1024, 0,   1024);
    prep_w<<<(1024 * 256  + 255) / 256, 256>>>(W3, pw3t, 1024, 512,  256, 256);

    for (int t = 0; t < T_STEPS; t++) {
        mma_gemm<1,128><<<dim3(32, 8), 256, SMEM128>>>(psr, pw1t, b1, ph1, 128,
                                                       W1, actions, t, nullptr);
        mma_gemm<0,128><<<dim3(32, 8), 256, SMEM128>>>(ph1, pw2t, b2, ph2, 1024,
                                                       nullptr, nullptr, 0, nullptr);
        mma_gemm<2,64><<<dim3(32, 4), 256, SMEM64>>>(ph2, pw3t, b3 + 256, nullptr, 1024,
                                                     nullptr, actions, t, out);
    }
}

// round 5
// speedup vs baseline: 6.0079x; 1.0150x over previous
#include <cuda_runtime.h>
#include <cuda_fp16.h>
#include <cstdint>

#define BATCH   4096
#define T_STEPS 64
#define NDIM    128
#define HID     1024
#define DT_C    0.1f

// ---------------- device scratch (no allocations allowed) -------------------
__device__ float g_s [BATCH * NDIM];                    // fp32 exact state
__device__ __align__(16) __half g_sr [BATCH * NDIM];    // fp16 state, A-tiled (K=128)
__device__ __align__(16) __half g_h1 [BATCH * HID];     // A-tiled (K=1024)
__device__ __align__(16) __half g_h2 [BATCH * HID];     // A-tiled (K=1024)
__device__ __align__(16) __half g_W1T[HID * NDIM];      // B-tiled N=1024,K=128
__device__ __align__(16) __half g_W2T[HID * HID];       // B-tiled N=1024,K=1024
__device__ __align__(16) __half g_W3T[256 * HID];       // B-tiled N=256,K=1024 (W3 cols 256..511)

// ---------------- static stream/event (created before harness checkpoints) --
static cudaStream_t g_aux = nullptr;
static cudaEvent_t  g_evF = nullptr, g_evJ = nullptr;
static struct AuxInit {
    AuxInit() {
        if (cudaStreamCreateWithFlags(&g_aux, cudaStreamNonBlocking) != cudaSuccess)
            g_aux = nullptr;
        if (cudaEventCreateWithFlags(&g_evF, cudaEventDisableTiming) != cudaSuccess)
            g_evF = nullptr;
        if (cudaEventCreateWithFlags(&g_evJ, cudaEventDisableTiming) != cudaSuccess)
            g_evJ = nullptr;
    }
} g_auxinit;

// ---------------- helpers ----------------------------------------------------
__device__ __forceinline__ uint32_t smem_u32(const void* p) {
    uint32_t a;
    asm("{ .reg .u64 t; cvta.to.shared.u64 t, %1; cvt.u32.u64 %0, t; }" : "=r"(a) : "l"(p));
    return a;
}
__device__ __forceinline__ void cp16(uint32_t dst, const void* src) {
    asm volatile("cp.async.cg.shared.global [%0], [%1], 16;" :: "r"(dst), "l"(src));
}
__device__ __forceinline__ void cp_commit() { asm volatile("cp.async.commit_group;"); }
template<int N> __device__ __forceinline__ void cp_wait() {
    asm volatile("cp.async.wait_group %0;" :: "n"(N) : "memory");
}

// mma.sync m16n8k16 fp16 in, fp32 acc: d += a*b
__device__ __forceinline__ void mma16(float (&d)[4], const uint32_t (&a)[4],
                                      const uint32_t (&b)[2]) {
    asm volatile(
        "mma.sync.aligned.m16n8k16.row.col.f32.f16.f16.f32 "
        "{%0,%1,%2,%3}, {%4,%5,%6,%7}, {%8,%9}, {%0,%1,%2,%3};"
        : "+f"(d[0]), "+f"(d[1]), "+f"(d[2]), "+f"(d[3])
        : "r"(a[0]), "r"(a[1]), "r"(a[2]), "r"(a[3]), "r"(b[0]), "r"(b[1]));
}

// Fragment-native tiled layouts (half element index).
__device__ __forceinline__ size_t a_idx_h(int m, int k, int K) {
    return ((size_t)(m >> 4) * (K >> 4) + (k >> 4)) * 256
         + (((m & 7) * 4 + ((k & 7) >> 1)) << 3)
         + ((((m >> 3) & 1) | (((k >> 3) & 1) << 1)) << 1) + (k & 1);
}
__device__ __forceinline__ size_t b_idx_h(int n, int k, int K) {
    return ((size_t)(n >> 3) * (K >> 4) + (k >> 4)) * 128
         + (((n & 7) * 4 + ((k & 7) >> 1)) << 2)
         + (((k >> 3) & 1) << 1) + (k & 1);
}

// ---------------------------------------------------------------------------
__global__ void init_kernel(const float* __restrict__ states, float* __restrict__ out) {
    int i = blockIdx.x * blockDim.x + threadIdx.x;
    if (i < BATCH * NDIM) {
        int b = i >> 7, n = i & 127;
        float v = states[(size_t)b * T_STEPS * NDIM + n];
        g_s[i] = v;
        g_sr[a_idx_h(b, n, NDIM)] = __float2half_rn(v);
        out[((size_t)b * (T_STEPS + 1)) * NDIM + n] = v;
    }
}

__global__ void prep_w(const float* __restrict__ in, __half* __restrict__ outp,
                       int K, int Nfull, int n0, int N) {
    int idx = blockIdx.x * blockDim.x + threadIdx.x;
    if (idx < K * N) {
        int n = idx % N, k = idx / N;
        outp[b_idx_h(n, k, K)] = __float2half_rn(in[(size_t)k * Nfull + n0 + n]);
    }
}

// ---------------------------------------------------------------------------
// fp16 mma.sync GEMM. Block tile 128 x NT, 8 warps, K-chunk 32, 4-stage pipe.
// bm0 = row-tile offset (dual-stream batch halves).
// MODE 0: C = fp16(relu(D+bias))                       (layer 2)
// MODE 1: + a0*W1[128,:] + a1*W1[129,:] rank-2 fold    (layer 1)
// MODE 2: P=D+bias; s += DT*(P_even*a0+P_odd*a1); write s, sr, out
// ---------------------------------------------------------------------------
template<int MODE, int NT>
__global__ void __launch_bounds__(256, 2)
mma_gemm(const __half* __restrict__ A, const __half* __restrict__ Bt,
         const float* __restrict__ bias, __half* __restrict__ C, int K,
         const float* __restrict__ W1raw, const float* __restrict__ actions,
         int t, float* __restrict__ out, int bm0)
{
    constexpr int OFF     = 4096;
    constexpr int A_BYTES = 8192;                        // 128 x 32 fp16
    constexpr int B_BYTES = NT * 32 * 2;
    constexpr int STAGE   = A_BYTES + B_BYTES;
    constexpr int MF      = (NT == 128) ? 4 : 2;
    constexpr int NBLK    = NT / 8;

    extern __shared__ char smem[];
    float* hS = (float*)smem;   // [0:128) bias, [128) a0, [256) a1, [384) w0, [512) w1
    const uint32_t sb = smem_u32(smem);
    const int tid = threadIdx.x, lane = tid & 31, warp = tid >> 5;
    const int wm = (NT == 128) ? (warp & 1) : (warp >> 1);
    const int wn = (NT == 128) ? (warp >> 1) : (warp & 1);
    const int bm = blockIdx.x + bm0, bn = blockIdx.y;
    const int KT   = K >> 5;
    const int KB16 = K >> 4;

    if (tid < NT)  hS[tid] = bias[bn * NT + tid];
    if (tid < 128 && MODE != 0) {
        int m = bm * 128 + tid;
        const float* ap = actions + ((size_t)m * T_STEPS + t) * 2;
        hS[128 + tid] = ap[0];
        hS[256 + tid] = ap[1];
    }
    if (tid < NT && MODE == 1) {
        hS[384 + tid] = W1raw[(size_t)128 * HID + bn * NT + tid];
        hS[512 + tid] = W1raw[(size_t)129 * HID + bn * NT + tid];
    }

    auto load_stage = [&](int ks) {
        uint32_t sa = sb + OFF + (uint32_t)(ks & 3) * STAGE;
        #pragma unroll
        for (int v = tid; v < 512; v += 256) {
            int i = v >> 6, inner = v & 63;
            cp16(sa + (uint32_t)v * 16,
                 A + ((size_t)(bm * 8 + i) * KB16 + 2 * ks) * 256 + inner * 8);
        }
        uint32_t sB = sa + A_BYTES;
        #pragma unroll
        for (int v = tid; v < NBLK * 32; v += 256) {
            int j = v >> 5, inner = v & 31;
            cp16(sB + (uint32_t)v * 16,
                 Bt + ((size_t)(bn * NBLK + j) * KB16 + 2 * ks) * 128 + inner * 8);
        }
        cp_commit();
    };

    float acc[MF][4][4];
    #pragma unroll
    for (int i = 0; i < MF; i++)
        #pragma unroll
        for (int j = 0; j < 4; j++)
            #pragma unroll
            for (int q = 0; q < 4; q++) acc[i][j][q] = 0.f;

    load_stage(0); load_stage(1); load_stage(2);

    for (int kt = 0; kt < KT; kt++) {
        int ahead = KT - 1 - kt;
        if (ahead >= 2) cp_wait<2>();
        else if (ahead == 1) cp_wait<1>();
        else cp_wait<0>();
        __syncthreads();

        if (kt + 3 < KT) load_stage(kt + 3);

        uint32_t sa = sb + OFF + (uint32_t)(kt & 3) * STAGE;
        uint32_t sB = sa + A_BYTES;
        #pragma unroll
        for (int kk = 0; kk < 2; kk++) {
            uint32_t afr[MF][4], bfr[4][2];
            #pragma unroll
            for (int mf = 0; mf < MF; mf++) {
                uint32_t ad = sa + (uint32_t)((wm * MF + mf) * 1024 + kk * 512) + lane * 16;
                asm volatile("ld.shared.v4.b32 {%0,%1,%2,%3}, [%4];"
                    : "=r"(afr[mf][0]), "=r"(afr[mf][1]), "=r"(afr[mf][2]), "=r"(afr[mf][3])
                    : "r"(ad));
            }
            #pragma unroll
            for (int nf = 0; nf < 4; nf++) {
                uint32_t bd = sB + (uint32_t)((wn * 4 + nf) * 512 + kk * 256) + lane * 8;
                asm volatile("ld.shared.v2.b32 {%0,%1}, [%2];"
                    : "=r"(bfr[nf][0]), "=r"(bfr[nf][1]) : "r"(bd));
            }
            #pragma unroll
            for (int mf = 0; mf < MF; mf++)
                #pragma unroll
                for (int nf = 0; nf < 4; nf++)
                    mma16(acc[mf][nf], afr[mf], bfr[nf]);
        }
    }

    const int r = lane >> 2, tig = lane & 3;

    if (MODE == 2) {
        #pragma unroll
        for (int mf = 0; mf < MF; mf++) {
            int ml = wm * (MF * 16) + mf * 16 + r;
            int m = bm * 128 + ml;
            float a0L = hS[128 + ml],     a1L = hS[256 + ml];
            float a0H = hS[128 + ml + 8], a1H = hS[256 + ml + 8];
            #pragma unroll
            for (int nf = 0; nf < 4; nf++) {
                int nl0 = wn * 32 + nf * 8 + tig * 2;
                int n = bn * (NT >> 1) + (nl0 >> 1);
                float p0 = acc[mf][nf][0] + hS[nl0];
                float p1 = acc[mf][nf][1] + hS[nl0 + 1];
                float p2 = acc[mf][nf][2] + hS[nl0];
                float p3 = acc[mf][nf][3] + hS[nl0 + 1];
                float sv0 = g_s[(size_t)m * NDIM + n];
                float sv1 = g_s[(size_t)(m + 8) * NDIM + n];
                float ns0 = fmaf(DT_C, fmaf(p0, a0L, p1 * a1L), sv0);
                float ns1 = fmaf(DT_C, fmaf(p2, a0H, p3 * a1H), sv1);
                g_s[(size_t)m * NDIM + n] = ns0;
                g_s[(size_t)(m + 8) * NDIM + n] = ns1;
                g_sr[a_idx_h(m, n, NDIM)] = __float2half_rn(ns0);
                g_sr[a_idx_h(m + 8, n, NDIM)] = __float2half_rn(ns1);
                out[((size_t)m * (T_STEPS + 1) + t + 1) * NDIM + n] = ns0;
                out[((size_t)(m + 8) * (T_STEPS + 1) + t + 1) * NDIM + n] = ns1;
            }
        }
        return;
    }

    // MODE 0/1: bias(+rank-2)+relu -> fp16, direct coalesced uint4 stores.
    // Per (mf, nf-pair): 8 halves land contiguously at block*256 + lane*8.
    const int KOUT = HID >> 4;   // 64
    #pragma unroll
    for (int mf = 0; mf < MF; mf++) {
        int ml = wm * (MF * 16) + mf * 16 + r;
        float a0L = 0.f, a1L = 0.f, a0H = 0.f, a1H = 0.f;
        if (MODE == 1) {
            a0L = hS[128 + ml];     a1L = hS[256 + ml];
            a0H = hS[128 + ml + 8]; a1H = hS[256 + ml + 8];
        }
        #pragma unroll
        for (int nfp = 0; nfp < 2; nfp++) {
            uint32_t q[4];
            #pragma unroll
            for (int h = 0; h < 2; h++) {
                int nf = nfp * 2 + h;
                int nl0 = wn * 32 + nf * 8 + tig * 2;
                float v00 = acc[mf][nf][0] + hS[nl0];
                float v01 = acc[mf][nf][1] + hS[nl0 + 1];
                float v10 = acc[mf][nf][2] + hS[nl0];
                float v11 = acc[mf][nf][3] + hS[nl0 + 1];
                if (MODE == 1) {
                    v00 += a0L * hS[384 + nl0]     + a1L * hS[512 + nl0];
                    v01 += a0L * hS[384 + nl0 + 1] + a1L * hS[512 + nl0 + 1];
                    v10 += a0H * hS[384 + nl0]     + a1H * hS[512 + nl0];
                    v11 += a0H * hS[384 + nl0 + 1] + a1H * hS[512 + nl0 + 1];
                }
                v00 = v00 > 0.f ? v00 : 0.f;  v01 = v01 > 0.f ? v01 : 0.f;
                v10 = v10 > 0.f ? v10 : 0.f;  v11 = v11 > 0.f ? v11 : 0.f;
                __half2 lo = __floats2half2_rn(v00, v01);
                __half2 hi = __floats2half2_rn(v10, v11);
                q[h * 2]     = *(uint32_t*)&lo;
                q[h * 2 + 1] = *(uint32_t*)&hi;
            }
            int mblk = (bm * 128 + ml) >> 4;
            int nblk = (bn * 128 + wn * 32 + nfp * 16) >> 4;
            size_t off = ((size_t)mblk * KOUT + nblk) * 256 + lane * 8;
            *(uint4*)&C[off] = make_uint4(q[0], q[1], q[2], q[3]);
        }
    }
}

// ---------------------------------------------------------------------------
extern "C" void kernel_launch(void* const* d_in, const int* in_sizes, int n_in,
                              void* d_out, int out_size) {
    const float* states  = (const float*)d_in[0];
    const float* actions = (const float*)d_in[1];
    const float* W1 = (const float*)d_in[2];
    const float* b1 = (const float*)d_in[3];
    const float* W2 = (const float*)d_in[4];
    const float* b2 = (const float*)d_in[5];
    const float* W3 = (const float*)d_in[6];
    const float* b3 = (const float*)d_in[7];
    float* out = (float*)d_out;

    __half *psr, *ph1, *ph2, *pw1t, *pw2t, *pw3t;
    cudaGetSymbolAddress((void**)&psr,  g_sr);
    cudaGetSymbolAddress((void**)&ph1,  g_h1);
    cudaGetSymbolAddress((void**)&ph2,  g_h2);
    cudaGetSymbolAddress((void**)&pw1t, g_W1T);
    cudaGetSymbolAddress((void**)&pw2t, g_W2T);
    cudaGetSymbolAddress((void**)&pw3t, g_W3T);

    const int SMEM128 = 4096 + 4 * (8192 + 8192);   // 69632
    const int SMEM64  = 4096 + 4 * (8192 + 4096);   // 53248
    cudaFuncSetAttribute(mma_gemm<0,128>, cudaFuncAttributeMaxDynamicSharedMemorySize, SMEM128);
    cudaFuncSetAttribute(mma_gemm<1,128>, cudaFuncAttributeMaxDynamicSharedMemorySize, SMEM128);
    cudaFuncSetAttribute(mma_gemm<2,64>,  cudaFuncAttributeMaxDynamicSharedMemorySize, SMEM64);

    init_kernel<<<(BATCH * NDIM + 255) / 256, 256>>>(states, out);
    prep_w<<<(128  * 1024 + 255) / 256, 256>>>(W1, pw1t, 128,  1024, 0,   1024);
    prep_w<<<(1024 * 1024 + 255) / 256, 256>>>(W2, pw2t, 1024, 1024, 0,   1024);
    prep_w<<<(1024 * 256  + 255) / 256, 256>>>(W3, pw3t, 1024, 512,  256, 256);

    const bool dual = (g_aux != nullptr) && (g_evF != nullptr) && (g_evJ != nullptr);
    cudaStream_t s1 = dual ? g_aux : (cudaStream_t)0;

    if (dual) {
        cudaEventRecord(g_evF, 0);
        cudaStreamWaitEvent(s1, g_evF, 0);
    }

    // chain H0 (rows 0..2047) on default stream, chain H1 on s1
    for (int t = 0; t < T_STEPS; t++) {
        mma_gemm<1,128><<<dim3(16, 8), 256, SMEM128, 0>>>(
            psr, pw1t, b1, ph1, 128, W1, actions, t, nullptr, 0);
        mma_gemm<0,128><<<dim3(16, 8), 256, SMEM128, 0>>>(
            ph1, pw2t, b2, ph2, 1024, nullptr, nullptr, 0, nullptr, 0);
        mma_gemm<2,64><<<dim3(16, 4), 256, SMEM64, 0>>>(
            ph2, pw3t, b3 + 256, nullptr, 1024, nullptr, actions, t, out, 0);
    }
    for (int t = 0; t < T_STEPS; t++) {
        mma_gemm<1,128><<<dim3(16, 8), 256, SMEM128, s1>>>(
            psr, pw1t, b1, ph1, 128, W1, actions, t, nullptr, 16);
        mma_gemm<0,128><<<dim3(16, 8), 256, SMEM128, s1>>>(
            ph1, pw2t, b2, ph2, 1024, nullptr, nullptr, 0, nullptr, 16);
        mma_gemm<2,64><<<dim3(16, 4), 256, SMEM64, s1>>>(
            ph2, pw3t, b3 + 256, nullptr, 1024, nullptr, actions, t, out, 16);
    }

    if (dual) {
        cudaEventRecord(g_evJ, s1);
        cudaStreamWaitEvent(0, g_evJ, 0);
    }
}

// round 6
// speedup vs baseline: 6.0085x; 1.0001x over previous
#include <cuda_runtime.h>
#include <cuda_fp16.h>
#include <cstdint>

#define BATCH   4096
#define T_STEPS 64
#define NDIM    128
#define HID     1024
#define DT_C    0.1f

// ---------------- device scratch (no allocations allowed) -------------------
__device__ float g_s [BATCH * NDIM];                    // fp32 exact state
__device__ __align__(16) __half g_sr [BATCH * NDIM];    // fp16 state, A-tiled (K=128)
__device__ __align__(16) __half g_h1 [BATCH * HID];     // A-tiled (K=1024)
__device__ __align__(16) __half g_h2 [BATCH * HID];     // A-tiled (K=1024)
__device__ __align__(16) __half g_W1T[HID * NDIM];      // B-tiled N=1024,K=128
__device__ __align__(16) __half g_W2T[HID * HID];       // B-tiled N=1024,K=1024
__device__ __align__(16) __half g_W3T[256 * HID];       // B-tiled N=256,K=1024 (W3 cols 256..511)

// ---------------- static streams/events (created before harness checkpoints) -
static cudaStream_t g_sA = nullptr, g_sB = nullptr;
static cudaEvent_t  g_evF = nullptr, g_evA = nullptr, g_evB = nullptr;
static struct AuxInit {
    AuxInit() {
        bool ok = true;
        ok &= cudaStreamCreateWithFlags(&g_sA, cudaStreamNonBlocking) == cudaSuccess;
        ok &= cudaStreamCreateWithFlags(&g_sB, cudaStreamNonBlocking) == cudaSuccess;
        ok &= cudaEventCreateWithFlags(&g_evF, cudaEventDisableTiming) == cudaSuccess;
        ok &= cudaEventCreateWithFlags(&g_evA, cudaEventDisableTiming) == cudaSuccess;
        ok &= cudaEventCreateWithFlags(&g_evB, cudaEventDisableTiming) == cudaSuccess;
        if (!ok) { g_sA = g_sB = nullptr; }
    }
} g_auxinit;

// ---------------- helpers ----------------------------------------------------
__device__ __forceinline__ uint32_t smem_u32(const void* p) {
    uint32_t a;
    asm("{ .reg .u64 t; cvta.to.shared.u64 t, %1; cvt.u32.u64 %0, t; }" : "=r"(a) : "l"(p));
    return a;
}
__device__ __forceinline__ void cp16(uint32_t dst, const void* src) {
    asm volatile("cp.async.cg.shared.global [%0], [%1], 16;" :: "r"(dst), "l"(src));
}
__device__ __forceinline__ void cp_commit() { asm volatile("cp.async.commit_group;"); }
template<int N> __device__ __forceinline__ void cp_wait() {
    asm volatile("cp.async.wait_group %0;" :: "n"(N) : "memory");
}

// mma.sync m16n8k16 fp16 in, fp32 acc: d += a*b
__device__ __forceinline__ void mma16(float (&d)[4], const uint32_t (&a)[4],
                                      const uint32_t (&b)[2]) {
    asm volatile(
        "mma.sync.aligned.m16n8k16.row.col.f32.f16.f16.f32 "
        "{%0,%1,%2,%3}, {%4,%5,%6,%7}, {%8,%9}, {%0,%1,%2,%3};"
        : "+f"(d[0]), "+f"(d[1]), "+f"(d[2]), "+f"(d[3])
        : "r"(a[0]), "r"(a[1]), "r"(a[2]), "r"(a[3]), "r"(b[0]), "r"(b[1]));
}

// Fragment-native tiled layouts (half element index).
__device__ __forceinline__ size_t a_idx_h(int m, int k, int K) {
    return ((size_t)(m >> 4) * (K >> 4) + (k >> 4)) * 256
         + (((m & 7) * 4 + ((k & 7) >> 1)) << 3)
         + ((((m >> 3) & 1) | (((k >> 3) & 1) << 1)) << 1) + (k & 1);
}
__device__ __forceinline__ size_t b_idx_h(int n, int k, int K) {
    return ((size_t)(n >> 3) * (K >> 4) + (k >> 4)) * 128
         + (((n & 7) * 4 + ((k & 7) >> 1)) << 2)
         + (((k >> 3) & 1) << 1) + (k & 1);
}

// ---------------------------------------------------------------------------
__global__ void init_kernel(const float* __restrict__ states, float* __restrict__ out) {
    int i = blockIdx.x * blockDim.x + threadIdx.x;
    if (i < BATCH * NDIM) {
        int b = i >> 7, n = i & 127;
        float v = states[(size_t)b * T_STEPS * NDIM + n];
        g_s[i] = v;
        g_sr[a_idx_h(b, n, NDIM)] = __float2half_rn(v);
        out[((size_t)b * (T_STEPS + 1)) * NDIM + n] = v;
    }
}

__global__ void prep_w(const float* __restrict__ in, __half* __restrict__ outp,
                       int K, int Nfull, int n0, int N) {
    int idx = blockIdx.x * blockDim.x + threadIdx.x;
    if (idx < K * N) {
        int n = idx % N, k = idx / N;
        outp[b_idx_h(n, k, K)] = __float2half_rn(in[(size_t)k * Nfull + n0 + n]);
    }
}

// ---------------------------------------------------------------------------
// fp16 mma.sync GEMM. Block tile 128 x NT, 8 warps, K-chunk 32, 4-stage pipe.
// bm0 = row-tile offset (dual-stream batch halves).
// MODE 0: C = fp16(relu(D+bias))                       (layer 2)
// MODE 1: + a0*W1[128,:] + a1*W1[129,:] rank-2 fold    (layer 1)
// MODE 2: P=D+bias; s += DT*(P_even*a0+P_odd*a1); write s, sr, out
// ---------------------------------------------------------------------------
template<int MODE, int NT>
__global__ void __launch_bounds__(256, 2)
mma_gemm(const __half* __restrict__ A, const __half* __restrict__ Bt,
         const float* __restrict__ bias, __half* __restrict__ C, int K,
         const float* __restrict__ W1raw, const float* __restrict__ actions,
         int t, float* __restrict__ out, int bm0)
{
    constexpr int OFF     = 4096;
    constexpr int A_BYTES = 8192;                        // 128 x 32 fp16
    constexpr int B_BYTES = NT * 32 * 2;
    constexpr int STAGE   = A_BYTES + B_BYTES;
    constexpr int MF      = (NT == 128) ? 4 : 2;
    constexpr int NBLK    = NT / 8;

    extern __shared__ char smem[];
    float* hS = (float*)smem;   // [0:128) bias, [128) a0, [256) a1, [384) w0, [512) w1
    const uint32_t sb = smem_u32(smem);
    const int tid = threadIdx.x, lane = tid & 31, warp = tid >> 5;
    const int wm = (NT == 128) ? (warp & 1) : (warp >> 1);
    const int wn = (NT == 128) ? (warp >> 1) : (warp & 1);
    const int bm = blockIdx.x + bm0, bn = blockIdx.y;
    const int KT   = K >> 5;
    const int KB16 = K >> 4;

    if (tid < NT)  hS[tid] = bias[bn * NT + tid];
    if (tid < 128 && MODE != 0) {
        int m = bm * 128 + tid;
        const float* ap = actions + ((size_t)m * T_STEPS + t) * 2;
        hS[128 + tid] = ap[0];
        hS[256 + tid] = ap[1];
    }
    if (tid < NT && MODE == 1) {
        hS[384 + tid] = W1raw[(size_t)128 * HID + bn * NT + tid];
        hS[512 + tid] = W1raw[(size_t)129 * HID + bn * NT + tid];
    }

    auto load_stage = [&](int ks) {
        uint32_t sa = sb + OFF + (uint32_t)(ks & 3) * STAGE;
        #pragma unroll
        for (int v = tid; v < 512; v += 256) {
            int i = v >> 6, inner = v & 63;
            cp16(sa + (uint32_t)v * 16,
                 A + ((size_t)(bm * 8 + i) * KB16 + 2 * ks) * 256 + inner * 8);
        }
        uint32_t sB = sa + A_BYTES;
        #pragma unroll
        for (int v = tid; v < NBLK * 32; v += 256) {
            int j = v >> 5, inner = v & 31;
            cp16(sB + (uint32_t)v * 16,
                 Bt + ((size_t)(bn * NBLK + j) * KB16 + 2 * ks) * 128 + inner * 8);
        }
        cp_commit();
    };

    float acc[MF][4][4];
    #pragma unroll
    for (int i = 0; i < MF; i++)
        #pragma unroll
        for (int j = 0; j < 4; j++)
            #pragma unroll
            for (int q = 0; q < 4; q++) acc[i][j][q] = 0.f;

    load_stage(0); load_stage(1); load_stage(2);

    for (int kt = 0; kt < KT; kt++) {
        int ahead = KT - 1 - kt;
        if (ahead >= 2) cp_wait<2>();
        else if (ahead == 1) cp_wait<1>();
        else cp_wait<0>();
        __syncthreads();

        if (kt + 3 < KT) load_stage(kt + 3);

        uint32_t sa = sb + OFF + (uint32_t)(kt & 3) * STAGE;
        uint32_t sB = sa + A_BYTES;
        #pragma unroll
        for (int kk = 0; kk < 2; kk++) {
            uint32_t afr[MF][4], bfr[4][2];
            #pragma unroll
            for (int mf = 0; mf < MF; mf++) {
                uint32_t ad = sa + (uint32_t)((wm * MF + mf) * 1024 + kk * 512) + lane * 16;
                asm volatile("ld.shared.v4.b32 {%0,%1,%2,%3}, [%4];"
                    : "=r"(afr[mf][0]), "=r"(afr[mf][1]), "=r"(afr[mf][2]), "=r"(afr[mf][3])
                    : "r"(ad));
            }
            #pragma unroll
            for (int nf = 0; nf < 4; nf++) {
                uint32_t bd = sB + (uint32_t)((wn * 4 + nf) * 512 + kk * 256) + lane * 8;
                asm volatile("ld.shared.v2.b32 {%0,%1}, [%2];"
                    : "=r"(bfr[nf][0]), "=r"(bfr[nf][1]) : "r"(bd));
            }
            #pragma unroll
            for (int mf = 0; mf < MF; mf++)
                #pragma unroll
                for (int nf = 0; nf < 4; nf++)
                    mma16(acc[mf][nf], afr[mf], bfr[nf]);
        }
    }

    const int r = lane >> 2, tig = lane & 3;

    if (MODE == 2) {
        #pragma unroll
        for (int mf = 0; mf < MF; mf++) {
            int ml = wm * (MF * 16) + mf * 16 + r;
            int m = bm * 128 + ml;
            float a0L = hS[128 + ml],     a1L = hS[256 + ml];
            float a0H = hS[128 + ml + 8], a1H = hS[256 + ml + 8];
            #pragma unroll
            for (int nf = 0; nf < 4; nf++) {
                int nl0 = wn * 32 + nf * 8 + tig * 2;
                int n = bn * (NT >> 1) + (nl0 >> 1);
                float p0 = acc[mf][nf][0] + hS[nl0];
                float p1 = acc[mf][nf][1] + hS[nl0 + 1];
                float p2 = acc[mf][nf][2] + hS[nl0];
                float p3 = acc[mf][nf][3] + hS[nl0 + 1];
                float sv0 = g_s[(size_t)m * NDIM + n];
                float sv1 = g_s[(size_t)(m + 8) * NDIM + n];
                float ns0 = fmaf(DT_C, fmaf(p0, a0L, p1 * a1L), sv0);
                float ns1 = fmaf(DT_C, fmaf(p2, a0H, p3 * a1H), sv1);
                g_s[(size_t)m * NDIM + n] = ns0;
                g_s[(size_t)(m + 8) * NDIM + n] = ns1;
                g_sr[a_idx_h(m, n, NDIM)] = __float2half_rn(ns0);
                g_sr[a_idx_h(m + 8, n, NDIM)] = __float2half_rn(ns1);
                out[((size_t)m * (T_STEPS + 1) + t + 1) * NDIM + n] = ns0;
                out[((size_t)(m + 8) * (T_STEPS + 1) + t + 1) * NDIM + n] = ns1;
            }
        }
        return;
    }

    // MODE 0/1: bias(+rank-2)+relu -> fp16, direct coalesced uint4 stores.
    const int KOUT = HID >> 4;   // 64
    #pragma unroll
    for (int mf = 0; mf < MF; mf++) {
        int ml = wm * (MF * 16) + mf * 16 + r;
        float a0L = 0.f, a1L = 0.f, a0H = 0.f, a1H = 0.f;
        if (MODE == 1) {
            a0L = hS[128 + ml];     a1L = hS[256 + ml];
            a0H = hS[128 + ml + 8]; a1H = hS[256 + ml + 8];
        }
        #pragma unroll
        for (int nfp = 0; nfp < 2; nfp++) {
            uint32_t q[4];
            #pragma unroll
            for (int h = 0; h < 2; h++) {
                int nf = nfp * 2 + h;
                int nl0 = wn * 32 + nf * 8 + tig * 2;
                float v00 = acc[mf][nf][0] + hS[nl0];
                float v01 = acc[mf][nf][1] + hS[nl0 + 1];
                float v10 = acc[mf][nf][2] + hS[nl0];
                float v11 = acc[mf][nf][3] + hS[nl0 + 1];
                if (MODE == 1) {
                    v00 += a0L * hS[384 + nl0]     + a1L * hS[512 + nl0];
                    v01 += a0L * hS[384 + nl0 + 1] + a1L * hS[512 + nl0 + 1];
                    v10 += a0H * hS[384 + nl0]     + a1H * hS[512 + nl0];
                    v11 += a0H * hS[384 + nl0 + 1] + a1H * hS[512 + nl0 + 1];
                }
                v00 = v00 > 0.f ? v00 : 0.f;  v01 = v01 > 0.f ? v01 : 0.f;
                v10 = v10 > 0.f ? v10 : 0.f;  v11 = v11 > 0.f ? v11 : 0.f;
                __half2 lo = __floats2half2_rn(v00, v01);
                __half2 hi = __floats2half2_rn(v10, v11);
                q[h * 2]     = *(uint32_t*)&lo;
                q[h * 2 + 1] = *(uint32_t*)&hi;
            }
            int mblk = (bm * 128 + ml) >> 4;
            int nblk = (bn * 128 + wn * 32 + nfp * 16) >> 4;
            size_t off = ((size_t)mblk * KOUT + nblk) * 256 + lane * 8;
            *(uint4*)&C[off] = make_uint4(q[0], q[1], q[2], q[3]);
        }
    }
}

// ---------------------------------------------------------------------------
static void run_chain(cudaStream_t s, int bm0,
                      const __half* psr, const __half* pw1t, const __half* pw2t,
                      const __half* pw3t, __half* ph1, __half* ph2,
                      const float* b1, const float* b2, const float* b3,
                      const float* W1, const float* actions, float* out,
                      int SMEM128, int SMEM64)
{
    for (int t = 0; t < T_STEPS; t++) {
        mma_gemm<1,128><<<dim3(16, 8), 256, SMEM128, s>>>(
            psr, pw1t, b1, ph1, 128, W1, actions, t, nullptr, bm0);
        mma_gemm<0,128><<<dim3(16, 8), 256, SMEM128, s>>>(
            ph1, pw2t, b2, ph2, 1024, nullptr, nullptr, 0, nullptr, bm0);
        mma_gemm<2,64><<<dim3(16, 4), 256, SMEM64, s>>>(
            ph2, pw3t, b3 + 256, nullptr, 1024, nullptr, actions, t, out, bm0);
    }
}

extern "C" void kernel_launch(void* const* d_in, const int* in_sizes, int n_in,
                              void* d_out, int out_size) {
    const float* states  = (const float*)d_in[0];
    const float* actions = (const float*)d_in[1];
    const float* W1 = (const float*)d_in[2];
    const float* b1 = (const float*)d_in[3];
    const float* W2 = (const float*)d_in[4];
    const float* b2 = (const float*)d_in[5];
    const float* W3 = (const float*)d_in[6];
    const float* b3 = (const float*)d_in[7];
    float* out = (float*)d_out;

    __half *psr, *ph1, *ph2, *pw1t, *pw2t, *pw3t;
    cudaGetSymbolAddress((void**)&psr,  g_sr);
    cudaGetSymbolAddress((void**)&ph1,  g_h1);
    cudaGetSymbolAddress((void**)&ph2,  g_h2);
    cudaGetSymbolAddress((void**)&pw1t, g_W1T);
    cudaGetSymbolAddress((void**)&pw2t, g_W2T);
    cudaGetSymbolAddress((void**)&pw3t, g_W3T);

    const int SMEM128 = 4096 + 4 * (8192 + 8192);   // 69632
    const int SMEM64  = 4096 + 4 * (8192 + 4096);   // 53248
    cudaFuncSetAttribute(mma_gemm<0,128>, cudaFuncAttributeMaxDynamicSharedMemorySize, SMEM128);
    cudaFuncSetAttribute(mma_gemm<1,128>, cudaFuncAttributeMaxDynamicSharedMemorySize, SMEM128);
    cudaFuncSetAttribute(mma_gemm<2,64>,  cudaFuncAttributeMaxDynamicSharedMemorySize, SMEM64);

    init_kernel<<<(BATCH * NDIM + 255) / 256, 256>>>(states, out);
    prep_w<<<(128  * 1024 + 255) / 256, 256>>>(W1, pw1t, 128,  1024, 0,   1024);
    prep_w<<<(1024 * 1024 + 255) / 256, 256>>>(W2, pw2t, 1024, 1024, 0,   1024);
    prep_w<<<(1024 * 256  + 255) / 256, 256>>>(W3, pw3t, 1024, 512,  256, 256);

    const bool dual = (g_sA != nullptr) && (g_sB != nullptr);

    if (dual) {
        // fork: both chains on NON-default streams (legacy stream 0 would
        // serialize against every other stream and kill the overlap)
        cudaEventRecord(g_evF, 0);
        cudaStreamWaitEvent(g_sA, g_evF, 0);
        cudaStreamWaitEvent(g_sB, g_evF, 0);

        run_chain(g_sA, 0,  psr, pw1t, pw2t, pw3t, ph1, ph2,
                  b1, b2, b3, W1, actions, out, SMEM128, SMEM64);
        run_chain(g_sB, 16, psr, pw1t, pw2t, pw3t, ph1, ph2,
                  b1, b2, b3, W1, actions, out, SMEM128, SMEM64);

        // join
        cudaEventRecord(g_evA, g_sA);
        cudaEventRecord(g_evB, g_sB);
        cudaStreamWaitEvent(0, g_evA, 0);
        cudaStreamWaitEvent(0, g_evB, 0);
    } else {
        run_chain(0, 0,  psr, pw1t, pw2t, pw3t, ph1, ph2,
                  b1, b2, b3, W1, actions, out, SMEM128, SMEM64);
        run_chain(0, 16, psr, pw1t, pw2t, pw3t, ph1, ph2,
                  b1, b2, b3, W1, actions, out, SMEM128, SMEM64);
    }
}

// round 7
// speedup vs baseline: 6.0760x; 1.0112x over previous
#include <cuda_runtime.h>
#include <cuda_fp16.h>
#include <cstdint>

#define BATCH   4096
#define T_STEPS 64
#define NDIM    128
#define HID     1024
#define DT_C    0.1f

// ---------------- device scratch (no allocations allowed) -------------------
__device__ float g_s [BATCH * NDIM];                    // fp32 exact state
__device__ __align__(16) __half g_sr [BATCH * NDIM];    // fp16 state, A-tiled (K=128)
__device__ __align__(16) __half g_h1 [BATCH * HID];     // A-tiled (K=1024)
__device__ __align__(16) __half g_h2 [BATCH * HID];     // A-tiled (K=1024)
__device__ __align__(16) __half g_W1T[HID * NDIM];      // B-tiled N=1024,K=128
__device__ __align__(16) __half g_W2T[HID * HID];       // B-tiled N=1024,K=1024
__device__ __align__(16) __half g_W3T[256 * HID];       // B-tiled N=256,K=1024 (W3 cols 256..511)

// ---------------- helpers ----------------------------------------------------
__device__ __forceinline__ uint32_t smem_u32(const void* p) {
    uint32_t a;
    asm("{ .reg .u64 t; cvta.to.shared.u64 t, %1; cvt.u32.u64 %0, t; }" : "=r"(a) : "l"(p));
    return a;
}
__device__ __forceinline__ void cp16(uint32_t dst, const void* src) {
    asm volatile("cp.async.cg.shared.global [%0], [%1], 16;" :: "r"(dst), "l"(src));
}
__device__ __forceinline__ void cp_commit() { asm volatile("cp.async.commit_group;"); }
template<int N> __device__ __forceinline__ void cp_wait() {
    asm volatile("cp.async.wait_group %0;" :: "n"(N) : "memory");
}

// mma.sync m16n8k16 fp16 in, fp32 acc: d += a*b
__device__ __forceinline__ void mma16(float (&d)[4], const uint32_t (&a)[4],
                                      const uint32_t (&b)[2]) {
    asm volatile(
        "mma.sync.aligned.m16n8k16.row.col.f32.f16.f16.f32 "
        "{%0,%1,%2,%3}, {%4,%5,%6,%7}, {%8,%9}, {%0,%1,%2,%3};"
        : "+f"(d[0]), "+f"(d[1]), "+f"(d[2]), "+f"(d[3])
        : "r"(a[0]), "r"(a[1]), "r"(a[2]), "r"(a[3]), "r"(b[0]), "r"(b[1]));
}

// Fragment-native tiled layouts (half element index).
__device__ __forceinline__ size_t a_idx_h(int m, int k, int K) {
    return ((size_t)(m >> 4) * (K >> 4) + (k >> 4)) * 256
         + (((m & 7) * 4 + ((k & 7) >> 1)) << 3)
         + ((((m >> 3) & 1) | (((k >> 3) & 1) << 1)) << 1) + (k & 1);
}
__device__ __forceinline__ size_t b_idx_h(int n, int k, int K) {
    return ((size_t)(n >> 3) * (K >> 4) + (k >> 4)) * 128
         + (((n & 7) * 4 + ((k & 7) >> 1)) << 2)
         + (((k >> 3) & 1) << 1) + (k & 1);
}

// ---------------------------------------------------------------------------
__global__ void init_kernel(const float* __restrict__ states, float* __restrict__ out) {
    int i = blockIdx.x * blockDim.x + threadIdx.x;
    if (i < BATCH * NDIM) {
        int b = i >> 7, n = i & 127;
        float v = states[(size_t)b * T_STEPS * NDIM + n];
        g_s[i] = v;
        g_sr[a_idx_h(b, n, NDIM)] = __float2half_rn(v);
        out[((size_t)b * (T_STEPS + 1)) * NDIM + n] = v;
    }
}

// all three weight preps in one kernel (fewer graph nodes; also shifts the
// ncu -s window onto the mainloop GEMMs)
__global__ void prep_all(const float* __restrict__ W1, const float* __restrict__ W2,
                         const float* __restrict__ W3,
                         __half* __restrict__ w1t, __half* __restrict__ w2t,
                         __half* __restrict__ w3t) {
    int idx = blockIdx.x * blockDim.x + threadIdx.x;
    const int NW2 = 1024 * 1024, NW3 = 256 * 1024, NW1 = 1024 * 128;
    if (idx < NW2) {
        int n = idx & 1023, k = idx >> 10;
        w2t[b_idx_h(n, k, 1024)] = __float2half_rn(W2[(size_t)k * 1024 + n]);
    } else if (idx < NW2 + NW3) {
        int r = idx - NW2;
        int n = r & 255, k = r >> 8;
        w3t[b_idx_h(n, k, 1024)] = __float2half_rn(W3[(size_t)k * 512 + 256 + n]);
    } else if (idx < NW2 + NW3 + NW1) {
        int r = idx - NW2 - NW3;
        int n = r & 1023, k = r >> 10;
        w1t[b_idx_h(n, k, 128)] = __float2half_rn(W1[(size_t)k * 1024 + n]);
    }
}

// ---------------------------------------------------------------------------
// fp16 mma.sync GEMM. Block tile 128 x NT, 8 warps, K-chunk 32.
// KTOT=128: full preload (no pipeline). KTOT=1024: 4-stage cp.async pipeline.
// MODE 0: C = fp16(relu(D+bias))                       (layer 2)
// MODE 1: + a0*W1[128,:] + a1*W1[129,:] rank-2 fold    (layer 1)
// MODE 2: P=D+bias; s += DT*(P_even*a0+P_odd*a1); write s, sr, out
// ---------------------------------------------------------------------------
template<int MODE, int NT, int KTOT>
__global__ void __launch_bounds__(256, 2)
mma_gemm(const __half* __restrict__ A, const __half* __restrict__ Bt,
         const float* __restrict__ bias, __half* __restrict__ C,
         const float* __restrict__ W1raw, const float* __restrict__ actions,
         int t, float* __restrict__ out)
{
    constexpr int OFF     = 4096;
    constexpr int A_BYTES = 8192;                        // 128 x 32 fp16
    constexpr int B_BYTES = NT * 32 * 2;
    constexpr int STAGE   = A_BYTES + B_BYTES;
    constexpr int MF      = (NT == 128) ? 4 : 2;
    constexpr int NBLK    = NT / 8;
    constexpr int KT      = KTOT >> 5;
    constexpr bool PRE    = (KTOT <= 128);               // whole K fits in 4 slots
    constexpr int KB16    = KTOT >> 4;

    extern __shared__ char smem[];
    float* hS = (float*)smem;   // [0:128) bias, [128) a0, [256) a1, [384) w0, [512) w1
    const uint32_t sb = smem_u32(smem);
    const int tid = threadIdx.x, lane = tid & 31, warp = tid >> 5;
    const int wm = (NT == 128) ? (warp & 1) : (warp >> 1);
    const int wn = (NT == 128) ? (warp >> 1) : (warp & 1);
    const int bm = blockIdx.x, bn = blockIdx.y;

    if (tid < NT)  hS[tid] = bias[bn * NT + tid];
    if (tid < 128 && MODE != 0) {
        int m = bm * 128 + tid;
        const float* ap = actions + ((size_t)m * T_STEPS + t) * 2;
        hS[128 + tid] = ap[0];
        hS[256 + tid] = ap[1];
    }
    if (tid < NT && MODE == 1) {
        hS[384 + tid] = W1raw[(size_t)128 * HID + bn * NT + tid];
        hS[512 + tid] = W1raw[(size_t)129 * HID + bn * NT + tid];
    }

    auto load_stage = [&](int ks) {
        uint32_t sa = sb + OFF + (uint32_t)(ks & 3) * STAGE;
        #pragma unroll
        for (int v = tid; v < 512; v += 256) {
            int i = v >> 6, inner = v & 63;
            cp16(sa + (uint32_t)v * 16,
                 A + ((size_t)(bm * 8 + i) * KB16 + 2 * ks) * 256 + inner * 8);
        }
        uint32_t sB = sa + A_BYTES;
        #pragma unroll
        for (int v = tid; v < NBLK * 32; v += 256) {
            int j = v >> 5, inner = v & 31;
            cp16(sB + (uint32_t)v * 16,
                 Bt + ((size_t)(bn * NBLK + j) * KB16 + 2 * ks) * 128 + inner * 8);
        }
        cp_commit();
    };

    float acc[MF][4][4];
    #pragma unroll
    for (int i = 0; i < MF; i++)
        #pragma unroll
        for (int j = 0; j < 4; j++)
            #pragma unroll
            for (int q = 0; q < 4; q++) acc[i][j][q] = 0.f;

    auto compute_chunk = [&](int kt) {
        uint32_t sa = sb + OFF + (uint32_t)(kt & 3) * STAGE;
        uint32_t sB = sa + A_BYTES;
        #pragma unroll
        for (int kk = 0; kk < 2; kk++) {
            uint32_t afr[MF][4], bfr[4][2];
            #pragma unroll
            for (int mf = 0; mf < MF; mf++) {
                uint32_t ad = sa + (uint32_t)((wm * MF + mf) * 1024 + kk * 512) + lane * 16;
                asm volatile("ld.shared.v4.b32 {%0,%1,%2,%3}, [%4];"
                    : "=r"(afr[mf][0]), "=r"(afr[mf][1]), "=r"(afr[mf][2]), "=r"(afr[mf][3])
                    : "r"(ad));
            }
            #pragma unroll
            for (int nf = 0; nf < 4; nf++) {
                uint32_t bd = sB + (uint32_t)((wn * 4 + nf) * 512 + kk * 256) + lane * 8;
                asm volatile("ld.shared.v2.b32 {%0,%1}, [%2];"
                    : "=r"(bfr[nf][0]), "=r"(bfr[nf][1]) : "r"(bd));
            }
            #pragma unroll
            for (int mf = 0; mf < MF; mf++)
                #pragma unroll
                for (int nf = 0; nf < 4; nf++)
                    mma16(acc[mf][nf], afr[mf], bfr[nf]);
        }
    };

    if (PRE) {
        // K fits entirely in the 4 stage slots: one wait, one sync, no bubbles.
        #pragma unroll
        for (int ks = 0; ks < KT; ks++) load_stage(ks);
        cp_wait<0>();
        __syncthreads();
        #pragma unroll
        for (int kt = 0; kt < KT; kt++) compute_chunk(kt);
    } else {
        load_stage(0); load_stage(1); load_stage(2);
        for (int kt = 0; kt < KT; kt++) {
            int ahead = KT - 1 - kt;
            if (ahead >= 2) cp_wait<2>();
            else if (ahead == 1) cp_wait<1>();
            else cp_wait<0>();
            __syncthreads();
            if (kt + 3 < KT) load_stage(kt + 3);
            compute_chunk(kt);
        }
    }

    const int r = lane >> 2, tig = lane & 3;

    if (MODE == 2) {
        #pragma unroll
        for (int mf = 0; mf < MF; mf++) {
            int ml = wm * (MF * 16) + mf * 16 + r;
            int m = bm * 128 + ml;
            float a0L = hS[128 + ml],     a1L = hS[256 + ml];
            float a0H = hS[128 + ml + 8], a1H = hS[256 + ml + 8];
            #pragma unroll
            for (int nf = 0; nf < 4; nf++) {
                int nl0 = wn * 32 + nf * 8 + tig * 2;
                int n = bn * (NT >> 1) + (nl0 >> 1);
                float p0 = acc[mf][nf][0] + hS[nl0];
                float p1 = acc[mf][nf][1] + hS[nl0 + 1];
                float p2 = acc[mf][nf][2] + hS[nl0];
                float p3 = acc[mf][nf][3] + hS[nl0 + 1];
                float sv0 = g_s[(size_t)m * NDIM + n];
                float sv1 = g_s[(size_t)(m + 8) * NDIM + n];
                float ns0 = fmaf(DT_C, fmaf(p0, a0L, p1 * a1L), sv0);
                float ns1 = fmaf(DT_C, fmaf(p2, a0H, p3 * a1H), sv1);
                g_s[(size_t)m * NDIM + n] = ns0;
                g_s[(size_t)(m + 8) * NDIM + n] = ns1;
                g_sr[a_idx_h(m, n, NDIM)] = __float2half_rn(ns0);
                g_sr[a_idx_h(m + 8, n, NDIM)] = __float2half_rn(ns1);
                out[((size_t)m * (T_STEPS + 1) + t + 1) * NDIM + n] = ns0;
                out[((size_t)(m + 8) * (T_STEPS + 1) + t + 1) * NDIM + n] = ns1;
            }
        }
        return;
    }

    // MODE 0/1: bias(+rank-2)+relu -> fp16, direct coalesced uint4 stores.
    const int KOUT = HID >> 4;   // 64
    #pragma unroll
    for (int mf = 0; mf < MF; mf++) {
        int ml = wm * (MF * 16) + mf * 16 + r;
        float a0L = 0.f, a1L = 0.f, a0H = 0.f, a1H = 0.f;
        if (MODE == 1) {
            a0L = hS[128 + ml];     a1L = hS[256 + ml];
            a0H = hS[128 + ml + 8]; a1H = hS[256 + ml + 8];
        }
        #pragma unroll
        for (int nfp = 0; nfp < 2; nfp++) {
            uint32_t q[4];
            #pragma unroll
            for (int h = 0; h < 2; h++) {
                int nf = nfp * 2 + h;
                int nl0 = wn * 32 + nf * 8 + tig * 2;
                float v00 = acc[mf][nf][0] + hS[nl0];
                float v01 = acc[mf][nf][1] + hS[nl0 + 1];
                float v10 = acc[mf][nf][2] + hS[nl0];
                float v11 = acc[mf][nf][3] + hS[nl0 + 1];
                if (MODE == 1) {
                    v00 += a0L * hS[384 + nl0]     + a1L * hS[512 + nl0];
                    v01 += a0L * hS[384 + nl0 + 1] + a1L * hS[512 + nl0 + 1];
                    v10 += a0H * hS[384 + nl0]     + a1H * hS[512 + nl0];
                    v11 += a0H * hS[384 + nl0 + 1] + a1H * hS[512 + nl0 + 1];
                }
                v00 = v00 > 0.f ? v00 : 0.f;  v01 = v01 > 0.f ? v01 : 0.f;
                v10 = v10 > 0.f ? v10 : 0.f;  v11 = v11 > 0.f ? v11 : 0.f;
                __half2 lo = __floats2half2_rn(v00, v01);
                __half2 hi = __floats2half2_rn(v10, v11);
                q[h * 2]     = *(uint32_t*)&lo;
                q[h * 2 + 1] = *(uint32_t*)&hi;
            }
            int mblk = (bm * 128 + ml) >> 4;
            int nblk = (bn * 128 + wn * 32 + nfp * 16) >> 4;
            size_t off = ((size_t)mblk * KOUT + nblk) * 256 + lane * 8;
            *(uint4*)&C[off] = make_uint4(q[0], q[1], q[2], q[3]);
        }
    }
}

// ---------------------------------------------------------------------------
extern "C" void kernel_launch(void* const* d_in, const int* in_sizes, int n_in,
                              void* d_out, int out_size) {
    const float* states  = (const float*)d_in[0];
    const float* actions = (const float*)d_in[1];
    const float* W1 = (const float*)d_in[2];
    const float* b1 = (const float*)d_in[3];
    const float* W2 = (const float*)d_in[4];
    const float* b2 = (const float*)d_in[5];
    const float* W3 = (const float*)d_in[6];
    const float* b3 = (const float*)d_in[7];
    float* out = (float*)d_out;

    __half *psr, *ph1, *ph2, *pw1t, *pw2t, *pw3t;
    cudaGetSymbolAddress((void**)&psr,  g_sr);
    cudaGetSymbolAddress((void**)&ph1,  g_h1);
    cudaGetSymbolAddress((void**)&ph2,  g_h2);
    cudaGetSymbolAddress((void**)&pw1t, g_W1T);
    cudaGetSymbolAddress((void**)&pw2t, g_W2T);
    cudaGetSymbolAddress((void**)&pw3t, g_W3T);

    const int SMEM128 = 4096 + 4 * (8192 + 8192);   // 69632
    const int SMEM64  = 4096 + 4 * (8192 + 4096);   // 53248
    cudaFuncSetAttribute((const void*)mma_gemm<0,128,1024>,
                         cudaFuncAttributeMaxDynamicSharedMemorySize, SMEM128);
    cudaFuncSetAttribute((const void*)mma_gemm<1,128,128>,
                         cudaFuncAttributeMaxDynamicSharedMemorySize, SMEM128);
    cudaFuncSetAttribute((const void*)mma_gemm<2,64,1024>,
                         cudaFuncAttributeMaxDynamicSharedMemorySize, SMEM64);

    init_kernel<<<(BATCH * NDIM + 255) / 256, 256>>>(states, out);
    const int PREP_N = 1024 * 1024 + 256 * 1024 + 1024 * 128;
    prep_all<<<(PREP_N + 255) / 256, 256>>>(W1, W2, W3, pw1t, pw2t, pw3t);

    for (int t = 0; t < T_STEPS; t++) {
        mma_gemm<1,128,128><<<dim3(32, 8), 256, SMEM128>>>(
            psr, pw1t, b1, ph1, W1, actions, t, nullptr);
        mma_gemm<0,128,1024><<<dim3(32, 8), 256, SMEM128>>>(
            ph1, pw2t, b2, ph2, nullptr, nullptr, 0, nullptr);
        mma_gemm<2,64,1024><<<dim3(32, 4), 256, SMEM64>>>(
            ph2, pw3t, b3 + 256, nullptr, nullptr, actions, t, out);
    }
}